// round 15
// baseline (speedup 1.0000x reference)
#include <cuda_runtime.h>
#include <cuda_bf16.h>

#define Nn 50000
#define Ee 800000
#define ET (Ee + Nn)
#define F 128
#define MB 64            // nodes per gemm block (2 blocks/SM co-resident)
#define AS 136           // smem row stride (bf16 elems), padded

// ---- scratch (device globals; no allocations) ----
// g_cnt relies on static zero-init; csr_scan re-zeros it after reading, so the
// "zero at entry" invariant holds across every call (incl. graph replays).
__device__ float         g_h   [Nn * F];
__device__ unsigned      g_bufh[Nn * 64];     // layer output, bf16 hi (2/word)
__device__ unsigned      g_bufl[Nn * 64];     // layer output, bf16 lo
__device__ float         g_al_s[Nn * 8];
__device__ float         g_al_d[Nn * 8];
__device__ int           g_cnt [Nn];
__device__ int           g_rp  [Nn + 1];
__device__ int           g_cur [Nn];
__device__ int           g_col [ET];
__device__ __nv_bfloat16 g_Whi [3 * F * F];   // W transposed [n][k], bf16 hi
__device__ __nv_bfloat16 g_Wlo [3 * F * F];   // bf16 lo

// ================= W pre-conversion (once) =================
__global__ void wconv(const float* __restrict__ W0, const float* __restrict__ W1,
                      const float* __restrict__ W2)
{
    int t = blockIdx.x * blockDim.x + threadIdx.x;
    if (t >= 3 * 2048) return;
    int l  = t / 2048;
    int r  = t % 2048;
    int n  = r % 128;
    int k0 = (r / 128) * 8;
    const float* W = (l == 0) ? W0 : (l == 1) ? W1 : W2;
    __align__(16) __nv_bfloat16 hi[8], lo[8];
#pragma unroll
    for (int j = 0; j < 8; j++) {
        float w = W[(k0 + j) * F + n];          // coalesced across lanes (n)
        hi[j] = __float2bfloat16_rn(w);
        lo[j] = __float2bfloat16_rn(w - __bfloat162float(hi[j]));
    }
    *reinterpret_cast<uint4*>(&g_Whi[l * F * F + n * F + k0]) =
        *reinterpret_cast<uint4*>(hi);
    *reinterpret_cast<uint4*>(&g_Wlo[l * F * F + n * F + k0]) =
        *reinterpret_cast<uint4*>(lo);
}

// ================= CSR build =================
__global__ void csr_hist(const int* __restrict__ ei)
{
    int e = blockIdx.x * blockDim.x + threadIdx.x;
    if (e >= ET) return;
    int dst = (e < Ee) ? ei[Ee + e] : e - Ee;
    atomicAdd(&g_cnt[dst], 1);
}

// coalesced tile-based exclusive scan; single block, 1024 threads.
__global__ void csr_scan()
{
    __shared__ int wsum[32];
    int t = threadIdx.x, lane = t & 31, w = t >> 5;
    int offset = 0;
    const int NT = (Nn + 1023) / 1024;
    for (int tile = 0; tile < NT; tile++) {
        int idx = tile * 1024 + t;
        int c = (idx < Nn) ? g_cnt[idx] : 0;
        int v = c;
#pragma unroll
        for (int o = 1; o < 32; o <<= 1) {
            int u = __shfl_up_sync(0xffffffffu, v, o);
            if (lane >= o) v += u;
        }
        if (lane == 31) wsum[w] = v;
        __syncthreads();
        if (w == 0) {
            int s = wsum[lane];
#pragma unroll
            for (int o = 1; o < 32; o <<= 1) {
                int u = __shfl_up_sync(0xffffffffu, s, o);
                if (lane >= o) s += u;
            }
            wsum[lane] = s;
        }
        __syncthreads();
        int excl = offset + (w > 0 ? wsum[w - 1] : 0) + v - c;
        if (idx < Nn) {
            g_rp[idx]  = excl;
            g_cur[idx] = excl;
            g_cnt[idx] = 0;      // restore invariant for next call
        }
        offset += wsum[31];
        __syncthreads();
    }
    if (t == 0) g_rp[Nn] = ET;
}

__global__ void csr_fill(const int* __restrict__ ei)
{
    int e = blockIdx.x * blockDim.x + threadIdx.x;
    if (e >= ET) return;
    int src, dst;
    if (e < Ee) { src = ei[e]; dst = ei[Ee + e]; }
    else        { src = dst = e - Ee; }
    int pos = atomicAdd(&g_cur[dst], 1);
    g_col[pos] = src;
}

// ================= tensor-core GEMM + attention logits =================
__device__ __forceinline__ void mma16816(float* d, unsigned a0, unsigned a1,
                                         unsigned a2, unsigned a3,
                                         unsigned b0, unsigned b1)
{
    asm volatile(
        "mma.sync.aligned.m16n8k16.row.col.f32.bf16.bf16.f32 "
        "{%0,%1,%2,%3},{%4,%5,%6,%7},{%8,%9},{%0,%1,%2,%3};"
        : "+f"(d[0]), "+f"(d[1]), "+f"(d[2]), "+f"(d[3])
        : "r"(a0), "r"(a1), "r"(a2), "r"(a3), "r"(b0), "r"(b1));
}

__global__ void __launch_bounds__(128)
gemm_tc(const float* __restrict__ xg, int layer,
        const float* __restrict__ asv,
        const float* __restrict__ adv, int H)
{
    extern __shared__ __nv_bfloat16 sm[];
    __nv_bfloat16* Ahi = sm;                    // [MB][AS]
    __nv_bfloat16* Alo = Ahi + MB * AS;
    __nv_bfloat16* Whi = Alo + MB * AS;         // [n=128][AS] (transposed)
    __nv_bfloat16* Wlo = Whi + F * AS;

    // device-side symbol access (host can't take &g_Whi)
    const __nv_bfloat16* whi = g_Whi + layer * F * F;
    const __nv_bfloat16* wlo = g_Wlo + layer * F * F;

    int tid   = threadIdx.x;
    int lane  = tid & 31;
    int warp  = tid >> 5;
    int g     = lane >> 2;      // groupID
    int t     = lane & 3;       // threadID in group
    int nbase = blockIdx.x * MB;

    // ---- stage A tile (64x128) ----
    if (layer > 0) {
        // pre-converted bf16 hi/lo: pure uint4 copy, no CVT
#pragma unroll
        for (int i = 0; i < 8; i++) {
            int lin = i * 128 + tid;            // uint4 index: 64 rows x 16
            int r = lin >> 4, q = lin & 15;
            uint4 zero = make_uint4(0u, 0u, 0u, 0u);
            uint4 vh = zero, vl = zero;
            if (nbase + r < Nn) {
                vh = *reinterpret_cast<const uint4*>(&g_bufh[(size_t)(nbase + r) * 64 + q * 4]);
                vl = *reinterpret_cast<const uint4*>(&g_bufl[(size_t)(nbase + r) * 64 + q * 4]);
            }
            *reinterpret_cast<uint4*>(&Ahi[r * AS + q * 8]) = vh;
            *reinterpret_cast<uint4*>(&Alo[r * AS + q * 8]) = vl;
        }
    } else {
        // layer 0: convert float x
#pragma unroll
        for (int i = 0; i < 16; i++) {
            int lin = i * 512 + tid * 4;
            int r   = lin >> 7, c = lin & 127;
            float4 xv = (nbase + r < Nn)
                ? *reinterpret_cast<const float4*>(&xg[(size_t)(nbase + r) * F + c])
                : make_float4(0.f, 0.f, 0.f, 0.f);
            __nv_bfloat16 h0 = __float2bfloat16_rn(xv.x);
            __nv_bfloat16 h1 = __float2bfloat16_rn(xv.y);
            __nv_bfloat16 h2 = __float2bfloat16_rn(xv.z);
            __nv_bfloat16 h3 = __float2bfloat16_rn(xv.w);
            __nv_bfloat16* ah = &Ahi[r * AS + c];
            __nv_bfloat16* al = &Alo[r * AS + c];
            ah[0] = h0; ah[1] = h1; ah[2] = h2; ah[3] = h3;
            al[0] = __float2bfloat16_rn(xv.x - __bfloat162float(h0));
            al[1] = __float2bfloat16_rn(xv.y - __bfloat162float(h1));
            al[2] = __float2bfloat16_rn(xv.z - __bfloat162float(h2));
            al[3] = __float2bfloat16_rn(xv.w - __bfloat162float(h3));
        }
    }
    // ---- stage W (pre-converted, pure copy) ----
#pragma unroll
    for (int i = 0; i < 16; i++) {
        int lin = i * 128 + tid;                // uint4 index: 128 rows x 16
        int n = lin >> 4, q = lin & 15;
        uint4 vh = *reinterpret_cast<const uint4*>(&whi[n * F + q * 8]);
        uint4 vl = *reinterpret_cast<const uint4*>(&wlo[n * F + q * 8]);
        *reinterpret_cast<uint4*>(&Whi[n * AS + q * 8]) = vh;
        *reinterpret_cast<uint4*>(&Wlo[n * AS + q * 8]) = vl;
    }
    __syncthreads();

    // ---- mainloop: each warp computes 16 rows x 128 cols ----
    int m0 = warp * 16;
    float d[16][4];
#pragma unroll
    for (int j = 0; j < 16; j++) { d[j][0] = d[j][1] = d[j][2] = d[j][3] = 0.f; }

    const unsigned* AhiU = reinterpret_cast<const unsigned*>(Ahi);
    const unsigned* AloU = reinterpret_cast<const unsigned*>(Alo);
    const unsigned* WhiU = reinterpret_cast<const unsigned*>(Whi);
    const unsigned* WloU = reinterpret_cast<const unsigned*>(Wlo);

    for (int ks = 0; ks < F; ks += 16) {
        int rowL = (m0 + g) * AS, rowH = (m0 + g + 8) * AS;
        int c0 = (ks + t * 2) >> 1;
        unsigned ah0 = AhiU[(rowL >> 1) + c0];
        unsigned ah1 = AhiU[(rowH >> 1) + c0];
        unsigned ah2 = AhiU[(rowL >> 1) + c0 + 4];
        unsigned ah3 = AhiU[(rowH >> 1) + c0 + 4];
        unsigned al0 = AloU[(rowL >> 1) + c0];
        unsigned al1 = AloU[(rowH >> 1) + c0];
        unsigned al2 = AloU[(rowL >> 1) + c0 + 4];
        unsigned al3 = AloU[(rowH >> 1) + c0 + 4];
#pragma unroll
        for (int j = 0; j < 16; j++) {
            int brow = ((j * 8 + g) * AS) >> 1;
            unsigned bh0 = WhiU[brow + c0];
            unsigned bh1 = WhiU[brow + c0 + 4];
            unsigned bl0 = WloU[brow + c0];
            unsigned bl1 = WloU[brow + c0 + 4];
            mma16816(d[j], ah0, ah1, ah2, ah3, bh0, bh1);
            mma16816(d[j], ah0, ah1, ah2, ah3, bl0, bl1);
            mma16816(d[j], al0, al1, al2, al3, bh0, bh1);
        }
    }

    // ---- epilogue: store h + per-head logits ----
    int nodeL = nbase + m0 + g;
    int nodeH = nodeL + 8;
#pragma unroll
    for (int j = 0; j < 16; j++) {
        int col = j * 8 + t * 2;
        if (nodeL < Nn)
            *reinterpret_cast<float2*>(&g_h[(size_t)nodeL * F + col]) =
                make_float2(d[j][0], d[j][1]);
        if (nodeH < Nn)
            *reinterpret_cast<float2*>(&g_h[(size_t)nodeH * F + col]) =
                make_float2(d[j][2], d[j][3]);
    }

    float tsL = 0.f, tdL = 0.f, tsH = 0.f, tdH = 0.f;
#pragma unroll
    for (int h = 0; h < 8; h++) {
        float psL = 0.f, pdL = 0.f, psH = 0.f, pdH = 0.f;
#pragma unroll
        for (int jj = 2 * h; jj <= 2 * h + 1; jj++) {
            int col = jj * 8 + t * 2;
            float2 av2 = *reinterpret_cast<const float2*>(&asv[col]);
            float2 dv2 = *reinterpret_cast<const float2*>(&adv[col]);
            psL += d[jj][0] * av2.x + d[jj][1] * av2.y;
            pdL += d[jj][0] * dv2.x + d[jj][1] * dv2.y;
            psH += d[jj][2] * av2.x + d[jj][3] * av2.y;
            pdH += d[jj][2] * dv2.x + d[jj][3] * dv2.y;
        }
        psL += __shfl_xor_sync(0xffffffffu, psL, 1);
        psL += __shfl_xor_sync(0xffffffffu, psL, 2);
        pdL += __shfl_xor_sync(0xffffffffu, pdL, 1);
        pdL += __shfl_xor_sync(0xffffffffu, pdL, 2);
        psH += __shfl_xor_sync(0xffffffffu, psH, 1);
        psH += __shfl_xor_sync(0xffffffffu, psH, 2);
        pdH += __shfl_xor_sync(0xffffffffu, pdH, 1);
        pdH += __shfl_xor_sync(0xffffffffu, pdH, 2);
        if (H == 8) {
            if (t == 0 && nodeL < Nn) {
                g_al_s[nodeL * 8 + h] = psL;
                g_al_d[nodeL * 8 + h] = pdL;
            }
            if (t == 0 && nodeH < Nn) {
                g_al_s[nodeH * 8 + h] = psH;
                g_al_d[nodeH * 8 + h] = pdH;
            }
        } else {
            tsL += psL; tdL += pdL; tsH += psH; tdH += pdH;
        }
    }
    if (H == 1 && t == 0) {
        if (nodeL < Nn) { g_al_s[nodeL * 8] = tsL; g_al_d[nodeL * 8] = tdL; }
        if (nodeH < Nn) { g_al_s[nodeH * 8] = tsH; g_al_d[nodeH * 8] = tdH; }
    }
}

// ================= fused per-node softmax-aggregate + LN (+ELU) =================
// one warp per dst node; zero-shuffle (R12 best). Writes bf16 hi/lo for the
// next layer's gemm, or float d_out for the final layer.
__global__ void node_agg(const float* __restrict__ b, const float* __restrict__ gg,
                         const float* __restrict__ be, float* __restrict__ out,
                         int do_elu, int H)
{
    int n = blockIdx.x * 8 + (threadIdx.x >> 5);
    if (n >= Nn) return;
    int lane  = threadIdx.x & 31;
    int hfeat = (H == 8) ? (lane >> 2) : 0;

    int begin = g_rp[n], end = g_rp[n + 1];
    float4 acc = make_float4(0.f, 0.f, 0.f, 0.f);
    float  ssum = 0.f;
    float  ald  = g_al_d[n * 8 + hfeat];
    const float* hb = g_h + lane * 4;

    int i = begin;
    for (; i + 2 <= end; i += 2) {
        int s0 = __ldg(&g_col[i]);
        int s1 = __ldg(&g_col[i + 1]);
        float a0 = __ldg(&g_al_s[s0 * 8 + hfeat]) + ald;
        float a1 = __ldg(&g_al_s[s1 * 8 + hfeat]) + ald;
        float4 h0 = *reinterpret_cast<const float4*>(hb + s0 * F);
        float4 h1 = *reinterpret_cast<const float4*>(hb + s1 * F);
        float e0 = __expf(fmaxf(a0, 0.2f * a0));   // exp(lrelu(.))
        float e1 = __expf(fmaxf(a1, 0.2f * a1));
        ssum += e0 + e1;
        acc.x += h0.x * e0 + h1.x * e1;
        acc.y += h0.y * e0 + h1.y * e1;
        acc.z += h0.z * e0 + h1.z * e1;
        acc.w += h0.w * e0 + h1.w * e1;
    }
    if (i < end) {
        int s0 = __ldg(&g_col[i]);
        float a0 = __ldg(&g_al_s[s0 * 8 + hfeat]) + ald;
        float4 h0 = *reinterpret_cast<const float4*>(hb + s0 * F);
        float e0 = __expf(fmaxf(a0, 0.2f * a0));
        ssum += e0;
        acc.x += h0.x * e0; acc.y += h0.y * e0; acc.z += h0.z * e0; acc.w += h0.w * e0;
    }

    float inv = 1.f / ssum;
    float4 bv = *reinterpret_cast<const float4*>(&b[lane * 4]);
    acc.x = acc.x * inv + bv.x;
    acc.y = acc.y * inv + bv.y;
    acc.z = acc.z * inv + bv.z;
    acc.w = acc.w * inv + bv.w;

    float tt = acc.x + acc.y + acc.z + acc.w;
#pragma unroll
    for (int o = 1; o < 32; o <<= 1) tt += __shfl_xor_sync(0xffffffffu, tt, o);
    float mu = tt * (1.f / F);
    float dx = acc.x - mu, dy = acc.y - mu, dz = acc.z - mu, dw = acc.w - mu;
    float v = dx * dx + dy * dy + dz * dz + dw * dw;
#pragma unroll
    for (int o = 1; o < 32; o <<= 1) v += __shfl_xor_sync(0xffffffffu, v, o);
    float rstd = rsqrtf(v * (1.f / F) + 1e-5f);

    float4 gv  = *reinterpret_cast<const float4*>(&gg[lane * 4]);
    float4 bev = *reinterpret_cast<const float4*>(&be[lane * 4]);
    float4 y;
    y.x = dx * rstd * gv.x + bev.x;
    y.y = dy * rstd * gv.y + bev.y;
    y.z = dz * rstd * gv.z + bev.z;
    y.w = dw * rstd * gv.w + bev.w;
    if (do_elu) {
        if (y.x < 0.f) y.x = __expf(y.x) - 1.f;
        if (y.y < 0.f) y.y = __expf(y.y) - 1.f;
        if (y.z < 0.f) y.z = __expf(y.z) - 1.f;
        if (y.w < 0.f) y.w = __expf(y.w) - 1.f;
    }

    if (out) {
        *reinterpret_cast<float4*>(&out[n * F + lane * 4]) = y;
    } else {
        // split-bf16 for the next gemm (identical math to converting there)
        __nv_bfloat162 h01 = __floats2bfloat162_rn(y.x, y.y);
        __nv_bfloat162 h23 = __floats2bfloat162_rn(y.z, y.w);
        float2 f01 = __bfloat1622float2(h01);
        float2 f23 = __bfloat1622float2(h23);
        __nv_bfloat162 l01 = __floats2bfloat162_rn(y.x - f01.x, y.y - f01.y);
        __nv_bfloat162 l23 = __floats2bfloat162_rn(y.z - f23.x, y.w - f23.y);
        uint2 vh, vl;
        vh.x = *reinterpret_cast<unsigned*>(&h01);
        vh.y = *reinterpret_cast<unsigned*>(&h23);
        vl.x = *reinterpret_cast<unsigned*>(&l01);
        vl.y = *reinterpret_cast<unsigned*>(&l23);
        *reinterpret_cast<uint2*>(&g_bufh[(size_t)n * 64 + lane * 2]) = vh;
        *reinterpret_cast<uint2*>(&g_bufl[(size_t)n * 64 + lane * 2]) = vl;
    }
}

extern "C" void kernel_launch(void* const* d_in, const int* in_sizes, int n_in,
                              void* d_out, int out_size)
{
    const float* x  = (const float*)d_in[0];
    const int*   ei = (const int*)d_in[1];

    const int SMEM = (2 * MB * AS + 2 * F * AS) * (int)sizeof(__nv_bfloat16);
    cudaFuncSetAttribute(gemm_tc, cudaFuncAttributeMaxDynamicSharedMemorySize, SMEM);

    wconv<<<24, 256>>>((const float*)d_in[2], (const float*)d_in[8],
                       (const float*)d_in[14]);
    csr_hist<<<(ET + 255) / 256, 256>>>(ei);
    csr_scan<<<1, 1024>>>();
    csr_fill<<<(ET + 255) / 256, 256>>>(ei);

    for (int l = 0; l < 3; l++) {
        const float* as_ = (const float*)d_in[3 + 6 * l];
        const float* ad_ = (const float*)d_in[4 + 6 * l];
        const float* b   = (const float*)d_in[5 + 6 * l];
        const float* g   = (const float*)d_in[6 + 6 * l];
        const float* be  = (const float*)d_in[7 + 6 * l];
        int H = (l == 2) ? 1 : 8;

        gemm_tc<<<(Nn + MB - 1) / MB, 128, SMEM>>>(x, l, as_, ad_, H);
        node_agg<<<(Nn + 7) / 8, 256>>>(b, g, be, (l == 2) ? (float*)d_out : nullptr,
                                        (l < 2) ? 1 : 0, H);
    }
}

// round 16
// speedup vs baseline: 1.5023x; 1.5023x over previous
#include <cuda_runtime.h>
#include <cuda_bf16.h>

#define Nn 50000
#define Ee 800000
#define ET (Ee + Nn)
#define F 128
#define MB 64            // nodes per gemm block
#define AS 136           // smem row stride (bf16 elems), padded

// ---- scratch (device globals; no allocations) ----
// g_cnt relies on static zero-init; csr_scan re-zeros it after reading, so the
// "zero at entry" invariant holds across every call (incl. graph replays).
__device__ float g_h   [Nn * F];
__device__ float g_buf [Nn * F];
__device__ float g_al_s[Nn * 8];
__device__ float g_al_d[Nn * 8];
__device__ int   g_cnt [Nn];
__device__ int   g_rp  [Nn + 1];
__device__ int   g_cur [Nn];
__device__ int   g_col [ET];

// ================= CSR build =================
__global__ void csr_hist(const int* __restrict__ ei)
{
    int e = blockIdx.x * blockDim.x + threadIdx.x;
    if (e >= ET) return;
    int dst = (e < Ee) ? ei[Ee + e] : e - Ee;
    atomicAdd(&g_cnt[dst], 1);
}

// coalesced tile-based exclusive scan; single block, 1024 threads.
__global__ void csr_scan()
{
    __shared__ int wsum[32];
    int t = threadIdx.x, lane = t & 31, w = t >> 5;
    int offset = 0;
    const int NT = (Nn + 1023) / 1024;
    for (int tile = 0; tile < NT; tile++) {
        int idx = tile * 1024 + t;
        int c = (idx < Nn) ? g_cnt[idx] : 0;
        int v = c;
#pragma unroll
        for (int o = 1; o < 32; o <<= 1) {
            int u = __shfl_up_sync(0xffffffffu, v, o);
            if (lane >= o) v += u;
        }
        if (lane == 31) wsum[w] = v;
        __syncthreads();
        if (w == 0) {
            int s = wsum[lane];
#pragma unroll
            for (int o = 1; o < 32; o <<= 1) {
                int u = __shfl_up_sync(0xffffffffu, s, o);
                if (lane >= o) s += u;
            }
            wsum[lane] = s;
        }
        __syncthreads();
        int excl = offset + (w > 0 ? wsum[w - 1] : 0) + v - c;
        if (idx < Nn) {
            g_rp[idx]  = excl;
            g_cur[idx] = excl;
            g_cnt[idx] = 0;      // restore invariant for next call
        }
        offset += wsum[31];
        __syncthreads();
    }
    if (t == 0) g_rp[Nn] = ET;
}

__global__ void csr_fill(const int* __restrict__ ei)
{
    int e = blockIdx.x * blockDim.x + threadIdx.x;
    if (e >= ET) return;
    int src, dst;
    if (e < Ee) { src = ei[e]; dst = ei[Ee + e]; }
    else        { src = dst = e - Ee; }
    int pos = atomicAdd(&g_cur[dst], 1);
    g_col[pos] = src;
}

// ================= tensor-core GEMM + attention logits =================
__device__ __forceinline__ void mma16816(float* d, unsigned a0, unsigned a1,
                                         unsigned a2, unsigned a3,
                                         unsigned b0, unsigned b1)
{
    asm volatile(
        "mma.sync.aligned.m16n8k16.row.col.f32.bf16.bf16.f32 "
        "{%0,%1,%2,%3},{%4,%5,%6,%7},{%8,%9},{%0,%1,%2,%3};"
        : "+f"(d[0]), "+f"(d[1]), "+f"(d[2]), "+f"(d[3])
        : "r"(a0), "r"(a1), "r"(a2), "r"(a3), "r"(b0), "r"(b1));
}

__device__ __forceinline__ void ldsm4(unsigned addr, unsigned& r0, unsigned& r1,
                                      unsigned& r2, unsigned& r3)
{
    asm volatile("ldmatrix.sync.aligned.m8n8.x4.shared.b16 {%0,%1,%2,%3}, [%4];"
                 : "=r"(r0), "=r"(r1), "=r"(r2), "=r"(r3) : "r"(addr));
}

__device__ __forceinline__ unsigned smem_u32(const void* p)
{
    return (unsigned)__cvta_generic_to_shared(p);
}

__global__ void __launch_bounds__(128)
gemm_tc(const float* __restrict__ xg, int use_buf,
        const float* __restrict__ W,
        const float* __restrict__ asv,
        const float* __restrict__ adv, int H)
{
    extern __shared__ __nv_bfloat16 sm[];
    __nv_bfloat16* Ahi = sm;                    // [MB][AS]
    __nv_bfloat16* Alo = Ahi + MB * AS;
    __nv_bfloat16* Whi = Alo + MB * AS;         // [n=128][AS] (transposed)
    __nv_bfloat16* Wlo = Whi + F * AS;

    const float* xin = use_buf ? g_buf : xg;
    int tid   = threadIdx.x;
    int lane  = tid & 31;
    int warp  = tid >> 5;
    int g     = lane >> 2;      // groupID
    int t     = lane & 3;       // threadID in group
    int nbase = blockIdx.x * MB;

    // ---- load + convert A (x tile 64x128) ----
#pragma unroll
    for (int i = 0; i < 16; i++) {
        int lin = i * 512 + tid * 4;
        int r   = lin >> 7, c = lin & 127;
        float4 xv = (nbase + r < Nn)
            ? *reinterpret_cast<const float4*>(&xin[(size_t)(nbase + r) * F + c])
            : make_float4(0.f, 0.f, 0.f, 0.f);
        __nv_bfloat16 h0 = __float2bfloat16_rn(xv.x);
        __nv_bfloat16 h1 = __float2bfloat16_rn(xv.y);
        __nv_bfloat16 h2 = __float2bfloat16_rn(xv.z);
        __nv_bfloat16 h3 = __float2bfloat16_rn(xv.w);
        __nv_bfloat16* ah = &Ahi[r * AS + c];
        __nv_bfloat16* al = &Alo[r * AS + c];
        ah[0] = h0; ah[1] = h1; ah[2] = h2; ah[3] = h3;
        al[0] = __float2bfloat16_rn(xv.x - __bfloat162float(h0));
        al[1] = __float2bfloat16_rn(xv.y - __bfloat162float(h1));
        al[2] = __float2bfloat16_rn(xv.z - __bfloat162float(h2));
        al[3] = __float2bfloat16_rn(xv.w - __bfloat162float(h3));
    }
    // ---- load + convert W (128x128), store transposed [n][k] ----
#pragma unroll
    for (int i = 0; i < 128; i++) {
        int lin = i * 128 + tid;
        int k = lin >> 7, n = lin & 127;
        float w = W[lin];
        __nv_bfloat16 h = __float2bfloat16_rn(w);
        __nv_bfloat16 l = __float2bfloat16_rn(w - __bfloat162float(h));
        Whi[n * AS + k] = h;
        Wlo[n * AS + k] = l;
    }
    __syncthreads();

    // ---- mainloop: each warp computes 16 rows x 128 cols (ldmatrix) ----
    int m0 = warp * 16;
    float d[16][4];
#pragma unroll
    for (int j = 0; j < 16; j++) { d[j][0] = d[j][1] = d[j][2] = d[j][3] = 0.f; }

    // A ldmatrix lane address: matrices {a0,a1,a2,a3} =
    //   (rows m0..7,k0-7),(m0+8..15,k0-7),(m0..7,k8-15),(m0+8..15,k8-15)
    int arow  = m0 + (lane & 7) + ((lane >> 3) & 1) * 8;
    int akoff = (lane >> 4) * 8;
    unsigned aHi = smem_u32(Ahi + arow * AS + akoff);
    unsigned aLo = smem_u32(Alo + arow * AS + akoff);

    // B ldmatrix lane addresses per j-pair p: matrices {b0(2p),b1(2p),b0(2p+1),b1(2p+1)}
    int bkoff = ((lane >> 3) & 1) * 8;
    int bnrow = (lane >> 4);            // 0 -> tile 2p, 1 -> tile 2p+1
    unsigned bHi[8], bLo[8];
#pragma unroll
    for (int p = 0; p < 8; p++) {
        int n = (2 * p + bnrow) * 8 + (lane & 7);
        bHi[p] = smem_u32(Whi + n * AS + bkoff);
        bLo[p] = smem_u32(Wlo + n * AS + bkoff);
    }

#pragma unroll
    for (int ks = 0; ks < F; ks += 16) {
        unsigned ah0, ah1, ah2, ah3, al0, al1, al2, al3;
        ldsm4(aHi + ks * 2, ah0, ah1, ah2, ah3);
        ldsm4(aLo + ks * 2, al0, al1, al2, al3);
#pragma unroll
        for (int p = 0; p < 8; p++) {
            unsigned bh0, bh1, bh2, bh3, bl0, bl1, bl2, bl3;
            ldsm4(bHi[p] + ks * 2, bh0, bh1, bh2, bh3);
            ldsm4(bLo[p] + ks * 2, bl0, bl1, bl2, bl3);
            mma16816(d[2 * p],     ah0, ah1, ah2, ah3, bh0, bh1);
            mma16816(d[2 * p],     ah0, ah1, ah2, ah3, bl0, bl1);
            mma16816(d[2 * p],     al0, al1, al2, al3, bh0, bh1);
            mma16816(d[2 * p + 1], ah0, ah1, ah2, ah3, bh2, bh3);
            mma16816(d[2 * p + 1], ah0, ah1, ah2, ah3, bl2, bl3);
            mma16816(d[2 * p + 1], al0, al1, al2, al3, bh2, bh3);
        }
    }

    // ---- epilogue: store h + per-head logits ----
    int nodeL = nbase + m0 + g;
    int nodeH = nodeL + 8;
#pragma unroll
    for (int j = 0; j < 16; j++) {
        int col = j * 8 + t * 2;
        if (nodeL < Nn)
            *reinterpret_cast<float2*>(&g_h[(size_t)nodeL * F + col]) =
                make_float2(d[j][0], d[j][1]);
        if (nodeH < Nn)
            *reinterpret_cast<float2*>(&g_h[(size_t)nodeH * F + col]) =
                make_float2(d[j][2], d[j][3]);
    }

    float tsL = 0.f, tdL = 0.f, tsH = 0.f, tdH = 0.f;
#pragma unroll
    for (int h = 0; h < 8; h++) {
        float psL = 0.f, pdL = 0.f, psH = 0.f, pdH = 0.f;
#pragma unroll
        for (int jj = 2 * h; jj <= 2 * h + 1; jj++) {
            int col = jj * 8 + t * 2;
            float2 av2 = *reinterpret_cast<const float2*>(&asv[col]);
            float2 dv2 = *reinterpret_cast<const float2*>(&adv[col]);
            psL += d[jj][0] * av2.x + d[jj][1] * av2.y;
            pdL += d[jj][0] * dv2.x + d[jj][1] * dv2.y;
            psH += d[jj][2] * av2.x + d[jj][3] * av2.y;
            pdH += d[jj][2] * dv2.x + d[jj][3] * dv2.y;
        }
        psL += __shfl_xor_sync(0xffffffffu, psL, 1);
        psL += __shfl_xor_sync(0xffffffffu, psL, 2);
        pdL += __shfl_xor_sync(0xffffffffu, pdL, 1);
        pdL += __shfl_xor_sync(0xffffffffu, pdL, 2);
        psH += __shfl_xor_sync(0xffffffffu, psH, 1);
        psH += __shfl_xor_sync(0xffffffffu, psH, 2);
        pdH += __shfl_xor_sync(0xffffffffu, pdH, 1);
        pdH += __shfl_xor_sync(0xffffffffu, pdH, 2);
        if (H == 8) {
            if (t == 0 && nodeL < Nn) {
                g_al_s[nodeL * 8 + h] = psL;
                g_al_d[nodeL * 8 + h] = pdL;
            }
            if (t == 0 && nodeH < Nn) {
                g_al_s[nodeH * 8 + h] = psH;
                g_al_d[nodeH * 8 + h] = pdH;
            }
        } else {
            tsL += psL; tdL += pdL; tsH += psH; tdH += pdH;
        }
    }
    if (H == 1 && t == 0) {
        if (nodeL < Nn) { g_al_s[nodeL * 8] = tsL; g_al_d[nodeL * 8] = tdL; }
        if (nodeH < Nn) { g_al_s[nodeH * 8] = tsH; g_al_d[nodeH * 8] = tdH; }
    }
}

// ================= fused per-node softmax-aggregate + LN (+ELU) =================
// one warp per dst node; zero-shuffle (R12 best)
__global__ void node_agg(const float* __restrict__ b, const float* __restrict__ gg,
                         const float* __restrict__ be, float* __restrict__ out,
                         int do_elu, int H)
{
    int n = blockIdx.x * 8 + (threadIdx.x >> 5);
    if (n >= Nn) return;
    int lane  = threadIdx.x & 31;
    int hfeat = (H == 8) ? (lane >> 2) : 0;

    int begin = g_rp[n], end = g_rp[n + 1];
    float4 acc = make_float4(0.f, 0.f, 0.f, 0.f);
    float  ssum = 0.f;
    float  ald  = g_al_d[n * 8 + hfeat];
    const float* hb = g_h + lane * 4;

    int i = begin;
    for (; i + 2 <= end; i += 2) {
        int s0 = __ldg(&g_col[i]);
        int s1 = __ldg(&g_col[i + 1]);
        float a0 = __ldg(&g_al_s[s0 * 8 + hfeat]) + ald;
        float a1 = __ldg(&g_al_s[s1 * 8 + hfeat]) + ald;
        float4 h0 = *reinterpret_cast<const float4*>(hb + s0 * F);
        float4 h1 = *reinterpret_cast<const float4*>(hb + s1 * F);
        float e0 = __expf(fmaxf(a0, 0.2f * a0));   // exp(lrelu(.))
        float e1 = __expf(fmaxf(a1, 0.2f * a1));
        ssum += e0 + e1;
        acc.x += h0.x * e0 + h1.x * e1;
        acc.y += h0.y * e0 + h1.y * e1;
        acc.z += h0.z * e0 + h1.z * e1;
        acc.w += h0.w * e0 + h1.w * e1;
    }
    if (i < end) {
        int s0 = __ldg(&g_col[i]);
        float a0 = __ldg(&g_al_s[s0 * 8 + hfeat]) + ald;
        float4 h0 = *reinterpret_cast<const float4*>(hb + s0 * F);
        float e0 = __expf(fmaxf(a0, 0.2f * a0));
        ssum += e0;
        acc.x += h0.x * e0; acc.y += h0.y * e0; acc.z += h0.z * e0; acc.w += h0.w * e0;
    }

    float inv = 1.f / ssum;
    float4 bv = *reinterpret_cast<const float4*>(&b[lane * 4]);
    acc.x = acc.x * inv + bv.x;
    acc.y = acc.y * inv + bv.y;
    acc.z = acc.z * inv + bv.z;
    acc.w = acc.w * inv + bv.w;

    float tt = acc.x + acc.y + acc.z + acc.w;
#pragma unroll
    for (int o = 1; o < 32; o <<= 1) tt += __shfl_xor_sync(0xffffffffu, tt, o);
    float mu = tt * (1.f / F);
    float dx = acc.x - mu, dy = acc.y - mu, dz = acc.z - mu, dw = acc.w - mu;
    float v = dx * dx + dy * dy + dz * dz + dw * dw;
#pragma unroll
    for (int o = 1; o < 32; o <<= 1) v += __shfl_xor_sync(0xffffffffu, v, o);
    float rstd = rsqrtf(v * (1.f / F) + 1e-5f);

    float4 gv  = *reinterpret_cast<const float4*>(&gg[lane * 4]);
    float4 bev = *reinterpret_cast<const float4*>(&be[lane * 4]);
    float4 y;
    y.x = dx * rstd * gv.x + bev.x;
    y.y = dy * rstd * gv.y + bev.y;
    y.z = dz * rstd * gv.z + bev.z;
    y.w = dw * rstd * gv.w + bev.w;
    if (do_elu) {
        if (y.x < 0.f) y.x = __expf(y.x) - 1.f;
        if (y.y < 0.f) y.y = __expf(y.y) - 1.f;
        if (y.z < 0.f) y.z = __expf(y.z) - 1.f;
        if (y.w < 0.f) y.w = __expf(y.w) - 1.f;
    }
    float* o = out ? out : g_buf;
    *reinterpret_cast<float4*>(&o[n * F + lane * 4]) = y;
}

extern "C" void kernel_launch(void* const* d_in, const int* in_sizes, int n_in,
                              void* d_out, int out_size)
{
    const float* x  = (const float*)d_in[0];
    const int*   ei = (const int*)d_in[1];

    const int SMEM = (2 * MB * AS + 2 * F * AS) * (int)sizeof(__nv_bfloat16);
    cudaFuncSetAttribute(gemm_tc, cudaFuncAttributeMaxDynamicSharedMemorySize, SMEM);

    csr_hist<<<(ET + 255) / 256, 256>>>(ei);
    csr_scan<<<1, 1024>>>();
    csr_fill<<<(ET + 255) / 256, 256>>>(ei);

    for (int l = 0; l < 3; l++) {
        const float* W   = (const float*)d_in[2 + 6 * l];
        const float* as_ = (const float*)d_in[3 + 6 * l];
        const float* ad_ = (const float*)d_in[4 + 6 * l];
        const float* b   = (const float*)d_in[5 + 6 * l];
        const float* g   = (const float*)d_in[6 + 6 * l];
        const float* be  = (const float*)d_in[7 + 6 * l];
        int H = (l == 2) ? 1 : 8;

        gemm_tc<<<(Nn + MB - 1) / MB, 128, SMEM>>>(x, l > 0 ? 1 : 0, W, as_, ad_, H);
        node_agg<<<(Nn + 7) / 8, 256>>>(b, g, be, (l == 2) ? (float*)d_out : nullptr,
                                        (l < 2) ? 1 : 0, H);
    }
}